// round 1
// baseline (speedup 1.0000x reference)
#include <cuda_runtime.h>
#include <math.h>

#define BB 8
#define CC 256
#define CIc 128
#define HH 64
#define WW 64
#define NN4 4096
#define MM 1024
#define EPSF 1e-5f
#define SCALE 0.08838834764831845f  // 1/sqrt(128)

// -------- scratch (static device globals; no allocation) --------
__device__ float d_xp[BB*CC*MM];        // pooled input  (b,c,m)
__device__ float d_theta[BB*CIc*NN4];   // (b,ci,n)
__device__ float d_phi[BB*CIc*MM];      // (b,ci,m)
__device__ float d_g[BB*CIc*MM];        // (b,ci,m)
__device__ float d_t[BB*CIc*NN4];       // attention output (b,ci,n)
__device__ float d_z[BB*CC*NN4];        // wz output (b,c,n)
__device__ float d_stats[2*CC];         // mean | rstd

// -------- 2x2 maxpool stride 2 --------
__global__ void pool_kernel(const float* __restrict__ x, float* __restrict__ xp){
    int e = blockIdx.x*256 + threadIdx.x;          // e < BB*CC*MM
    int p = e & 1023; int bc = e >> 10;
    int i = p >> 5, j = p & 31;
    const float* base = x + ((bc*HH + 2*i)*WW + 2*j);
    xp[e] = fmaxf(fmaxf(base[0], base[1]), fmaxf(base[WW], base[WW+1]));
}

// -------- generic 1x1 conv GEMM: Y[b] = W(CO,CIN) @ X[b](CIN,N) + bias --------
template<int CO, int CIN, int NPIX>
__global__ __launch_bounds__(256) void conv1x1_kernel(
        const float* __restrict__ X, const float* __restrict__ Wt,
        const float* __restrict__ bias, float* __restrict__ Y){
    __shared__ float Ws[16][64];
    __shared__ float Xs[16][64];
    int b  = blockIdx.z;
    const float* Xb = X + (size_t)b*CIN*NPIX;
    float* Yb = Y + (size_t)b*CO*NPIX;
    int n0 = blockIdx.x*64, m0 = blockIdx.y*64;
    int tid = threadIdx.x;
    int tx = tid & 15, ty = tid >> 4;
    int row = ty*4, col = tx*4;
    int wm = tid >> 2, wk = (tid & 3)*4;
    int xk = tid >> 4, xn = (tid & 15)*4;
    float acc[4][4] = {};
    for (int k0 = 0; k0 < CIN; k0 += 16){
        float4 wv = *(const float4*)&Wt[(m0+wm)*CIN + k0 + wk];
        Ws[wk  ][wm] = wv.x; Ws[wk+1][wm] = wv.y;
        Ws[wk+2][wm] = wv.z; Ws[wk+3][wm] = wv.w;
        *(float4*)&Xs[xk][xn] = *(const float4*)&Xb[(size_t)(k0+xk)*NPIX + n0 + xn];
        __syncthreads();
        #pragma unroll
        for (int k = 0; k < 16; k++){
            float4 av = *(const float4*)&Ws[k][row];
            float4 bv = *(const float4*)&Xs[k][col];
            float aarr[4] = {av.x, av.y, av.z, av.w};
            float barr[4] = {bv.x, bv.y, bv.z, bv.w};
            #pragma unroll
            for (int i = 0; i < 4; i++)
                #pragma unroll
                for (int j = 0; j < 4; j++)
                    acc[i][j] += aarr[i]*barr[j];
        }
        __syncthreads();
    }
    #pragma unroll
    for (int i = 0; i < 4; i++){
        float bvl = bias[m0+row+i];
        float4 o = make_float4(acc[i][0]+bvl, acc[i][1]+bvl, acc[i][2]+bvl, acc[i][3]+bvl);
        *(float4*)&Yb[(size_t)(m0+row+i)*NPIX + n0 + col] = o;
    }
}

// -------- attention: per (batch, 32-query tile), full 32x1024 scores in smem --------
#define SS_PITCH 1025
#define QS_OFF   (32*SS_PITCH)          // 32800
#define KG_OFF   (QS_OFF + 128*32)      // 36896
#define ATTN_SMEM_FLOATS (KG_OFF + 64*132)  // 36896 + 8448 = 45344
#define ATTN_SMEM_BYTES  (ATTN_SMEM_FLOATS*4)

__global__ __launch_bounds__(256) void attn_kernel(
        const float* __restrict__ theta, const float* __restrict__ phi,
        const float* __restrict__ g, float* __restrict__ t){
    extern __shared__ float sm[];
    float* Ss = sm;             // [32][1025]
    float* Qs = sm + QS_OFF;    // [128][32]
    float* KG = sm + KG_OFF;    // Ks[128][64] then Gs[64][132]
    int b  = blockIdx.y;
    int q0 = blockIdx.x*32;
    int tid = threadIdx.x;
    const float* thb = theta + (size_t)b*CIc*NN4;
    const float* phb = phi   + (size_t)b*CIc*MM;
    const float* gbp = g     + (size_t)b*CIc*MM;

    // load Q tile (scaled by 1/sqrt(CI))
    for (int i = tid; i < 128*32; i += 256){
        int d = i >> 5, q = i & 31;
        Qs[i] = thb[(size_t)d*NN4 + q0 + q] * SCALE;
    }

    // ---- phase B: scores S = Q^T K ----
    int q2 = (tid >> 4)*2;
    int k4 = (tid & 15)*4;
    for (int mt = 0; mt < 16; mt++){
        int m0 = mt*64;
        __syncthreads();   // prev compute done (and Qs loaded on first iter)
        for (int i = tid; i < 128*64; i += 256){
            int d = i >> 6, kk = i & 63;
            KG[i] = phb[(size_t)d*MM + m0 + kk];
        }
        __syncthreads();
        float acc[2][4] = {};
        #pragma unroll 4
        for (int d = 0; d < 128; d++){
            float qa = Qs[d*32 + q2];
            float qb = Qs[d*32 + q2 + 1];
            float4 kv = *(const float4*)&KG[d*64 + k4];
            acc[0][0] += qa*kv.x; acc[0][1] += qa*kv.y;
            acc[0][2] += qa*kv.z; acc[0][3] += qa*kv.w;
            acc[1][0] += qb*kv.x; acc[1][1] += qb*kv.y;
            acc[1][2] += qb*kv.z; acc[1][3] += qb*kv.w;
        }
        float* r0 = &Ss[q2*SS_PITCH + m0 + k4];
        r0[0]=acc[0][0]; r0[1]=acc[0][1]; r0[2]=acc[0][2]; r0[3]=acc[0][3];
        float* r1 = r0 + SS_PITCH;
        r1[0]=acc[1][0]; r1[1]=acc[1][1]; r1[2]=acc[1][2]; r1[3]=acc[1][3];
    }
    __syncthreads();

    // ---- phase C: softmax rows ----
    int warp = tid >> 5, lane = tid & 31;
    for (int r = warp; r < 32; r += 8){
        float* rowp = &Ss[r*SS_PITCH];
        float mx = -1e30f;
        for (int i = lane; i < 1024; i += 32) mx = fmaxf(mx, rowp[i]);
        #pragma unroll
        for (int o = 16; o; o >>= 1) mx = fmaxf(mx, __shfl_xor_sync(0xffffffffu, mx, o));
        float sum = 0.f;
        for (int i = lane; i < 1024; i += 32){
            float e = __expf(rowp[i] - mx); rowp[i] = e; sum += e;
        }
        #pragma unroll
        for (int o = 16; o; o >>= 1) sum += __shfl_xor_sync(0xffffffffu, sum, o);
        float inv = 1.f/sum;
        for (int i = lane; i < 1024; i += 32) rowp[i] *= inv;
    }

    // ---- phase D: t = G @ P^T ----
    int dd = (tid >> 3)*4;      // 0..124
    int qb = tid & 7;           // q = qb + 8*qj
    float acc2[4][4] = {};
    for (int mt = 0; mt < 16; mt++){
        int m0 = mt*64;
        __syncthreads();   // prev compute done (first: softmax done before Gs overwrite of Ks)
        for (int i = tid; i < 128*64; i += 256){
            int d = i >> 6, mm = i & 63;
            KG[mm*132 + d] = gbp[(size_t)d*MM + m0 + mm];
        }
        __syncthreads();
        for (int mm = 0; mm < 64; mm++){
            float4 gv = *(const float4*)&KG[mm*132 + dd];
            float ga[4] = {gv.x, gv.y, gv.z, gv.w};
            #pragma unroll
            for (int qj = 0; qj < 4; qj++){
                float pv = Ss[(qb + 8*qj)*SS_PITCH + m0 + mm];
                acc2[0][qj] += ga[0]*pv;
                acc2[1][qj] += ga[1]*pv;
                acc2[2][qj] += ga[2]*pv;
                acc2[3][qj] += ga[3]*pv;
            }
        }
    }
    float* tb = t + (size_t)b*CIc*NN4;
    #pragma unroll
    for (int di = 0; di < 4; di++)
        #pragma unroll
        for (int qj = 0; qj < 4; qj++)
            tb[(size_t)(dd+di)*NN4 + q0 + qb + 8*qj] = acc2[di][qj];
}

// -------- per-channel batch statistics (fp64 accumulate, deterministic) --------
__global__ void stats_kernel(const float* __restrict__ z, float* __restrict__ stats){
    __shared__ double sd[256], sd2[256];
    int c = blockIdx.x, tid = threadIdx.x;
    double s = 0.0, s2 = 0.0;
    for (int i = tid; i < BB*NN4; i += 256){
        int b = i >> 12, n = i & 4095;
        float v = z[((size_t)b*CC + c)*NN4 + n];
        s += v; s2 += (double)v*v;
    }
    sd[tid] = s; sd2[tid] = s2;
    __syncthreads();
    for (int o = 128; o; o >>= 1){
        if (tid < o){ sd[tid] += sd[tid+o]; sd2[tid] += sd2[tid+o]; }
        __syncthreads();
    }
    if (tid == 0){
        double cnt = (double)(BB*NN4);
        double mean = sd[0]/cnt;
        double var  = sd2[0]/cnt - mean*mean;
        stats[c]      = (float)mean;
        stats[CC + c] = rsqrtf((float)var + EPSF);
    }
}

// -------- normalize + affine + residual --------
__global__ void finalize_kernel(const float* __restrict__ x, const float* __restrict__ z,
                                const float* __restrict__ stats,
                                const float* __restrict__ gamma, const float* __restrict__ beta,
                                float* __restrict__ out){
    int i4 = blockIdx.x*256 + threadIdx.x;     // < BB*CC*NN4/4
    int c = (i4 >> 10) & 255;
    float a  = stats[CC + c] * gamma[c];
    float bc = beta[c] - stats[c]*a;
    float4 xv = ((const float4*)x)[i4];
    float4 zv = ((const float4*)z)[i4];
    float4 o;
    o.x = xv.x + zv.x*a + bc;
    o.y = xv.y + zv.y*a + bc;
    o.z = xv.z + zv.z*a + bc;
    o.w = xv.w + zv.w*a + bc;
    ((float4*)out)[i4] = o;
}

extern "C" void kernel_launch(void* const* d_in, const int* in_sizes, int n_in,
                              void* d_out, int out_size){
    const float* x       = (const float*)d_in[0];
    const float* theta_w = (const float*)d_in[1];
    const float* theta_b = (const float*)d_in[2];
    const float* phi_w   = (const float*)d_in[3];
    const float* phi_b   = (const float*)d_in[4];
    const float* g_w     = (const float*)d_in[5];
    const float* g_b     = (const float*)d_in[6];
    const float* wz_w    = (const float*)d_in[7];
    const float* wz_b    = (const float*)d_in[8];
    const float* gamma   = (const float*)d_in[9];
    const float* beta    = (const float*)d_in[10];
    float* out = (float*)d_out;

    float *xp, *theta, *phi, *g, *t, *z, *stats;
    cudaGetSymbolAddress((void**)&xp,    d_xp);
    cudaGetSymbolAddress((void**)&theta, d_theta);
    cudaGetSymbolAddress((void**)&phi,   d_phi);
    cudaGetSymbolAddress((void**)&g,     d_g);
    cudaGetSymbolAddress((void**)&t,     d_t);
    cudaGetSymbolAddress((void**)&z,     d_z);
    cudaGetSymbolAddress((void**)&stats, d_stats);

    cudaFuncSetAttribute(attn_kernel, cudaFuncAttributeMaxDynamicSharedMemorySize,
                         ATTN_SMEM_BYTES);

    pool_kernel<<<(BB*CC*MM)/256, 256>>>(x, xp);
    conv1x1_kernel<CIc, CC, NN4><<<dim3(NN4/64, CIc/64, BB), 256>>>(x,  theta_w, theta_b, theta);
    conv1x1_kernel<CIc, CC, MM ><<<dim3(MM/64,  CIc/64, BB), 256>>>(xp, phi_w,   phi_b,   phi);
    conv1x1_kernel<CIc, CC, MM ><<<dim3(MM/64,  CIc/64, BB), 256>>>(xp, g_w,     g_b,     g);
    attn_kernel<<<dim3(NN4/32, BB), 256, ATTN_SMEM_BYTES>>>(theta, phi, g, t);
    conv1x1_kernel<CC, CIc, NN4><<<dim3(NN4/64, CC/64, BB), 256>>>(t, wz_w, wz_b, z);
    stats_kernel<<<CC, 256>>>(z, stats);
    finalize_kernel<<<(BB*CC*NN4/4)/256, 256>>>(x, z, stats, gamma, beta, out);
}

// round 3
// speedup vs baseline: 1.1811x; 1.1811x over previous
#include <cuda_runtime.h>
#include <math.h>

#define BB 8
#define CC 256
#define CIc 128
#define HH 64
#define WW 64
#define NN4 4096
#define MM 1024
#define EPSF 1e-5f
#define SCALE 0.08838834764831845f  // 1/sqrt(128)

// -------- scratch (static device globals; no allocation) --------
__device__ float d_xp[BB*CC*MM];
__device__ float d_theta[BB*CIc*NN4];
__device__ float d_phi[BB*CIc*MM];
__device__ float d_g[BB*CIc*MM];
__device__ float d_t[BB*CIc*NN4];
__device__ float d_z[BB*CC*NN4];
__device__ float d_stats[2*CC];

// -------- helpers --------
__device__ __forceinline__ unsigned f2tf(float f){
    unsigned r; asm("cvt.rna.tf32.f32 %0, %1;" : "=r"(r) : "f"(f)); return r;
}
// split fp32 -> (hi, lo) tf32 pair
__device__ __forceinline__ void tfsplit(float v, unsigned &hi, unsigned &lo){
    hi = f2tf(v);
    lo = f2tf(v - __uint_as_float(hi));
}
__device__ __forceinline__ void mma_tf32(float c[4], unsigned a0, unsigned a1,
                                         unsigned a2, unsigned a3,
                                         unsigned b0, unsigned b1){
    asm("mma.sync.aligned.m16n8k8.row.col.f32.tf32.tf32.f32 "
        "{%0,%1,%2,%3},{%4,%5,%6,%7},{%8,%9},{%0,%1,%2,%3};"
        : "+f"(c[0]), "+f"(c[1]), "+f"(c[2]), "+f"(c[3])
        : "r"(a0), "r"(a1), "r"(a2), "r"(a3), "r"(b0), "r"(b1));
}
// 3xTF32: c += A*B with A=(ah,al), B=(bh,bl)
__device__ __forceinline__ void mma3(float c[4],
        const unsigned ah[4], const unsigned al[4],
        unsigned bh0, unsigned bh1, unsigned bl0, unsigned bl1){
    mma_tf32(c, ah[0],ah[1],ah[2],ah[3], bh0,bh1);
    mma_tf32(c, ah[0],ah[1],ah[2],ah[3], bl0,bl1);
    mma_tf32(c, al[0],al[1],al[2],al[3], bh0,bh1);
}

// -------- 2x2 maxpool stride 2 --------
__global__ void pool_kernel(const float* __restrict__ x, float* __restrict__ xp){
    int e = blockIdx.x*256 + threadIdx.x;
    int p = e & 1023; int bc = e >> 10;
    int i = p >> 5, j = p & 31;
    const float* base = x + ((bc*HH + 2*i)*WW + 2*j);
    xp[e] = fmaxf(fmaxf(base[0], base[1]), fmaxf(base[WW], base[WW+1]));
}

// -------- 1x1 conv, 3xTF32: Y[b](CO,N) = W @ X[b] + bias --------
// block tile 64(M) x 128(N), 8 warps 2x4, warp tile 32x32; raw fp32 tiles, register split
template<int CO, int CIN, int NPIX>
__global__ __launch_bounds__(256) void conv_mma(
        const float* __restrict__ X, const float* __restrict__ Wt,
        const float* __restrict__ bias, float* __restrict__ Y){
    __shared__ float Ws[32][68];    // [k][m]
    __shared__ float Xs[32][132];   // [k][n]
    int b = blockIdx.z;
    const float* Xb = X + (size_t)b*CIN*NPIX;
    float* Yb = Y + (size_t)b*CO*NPIX;
    int m0b = blockIdx.y*64, n0b = blockIdx.x*128;
    int tid = threadIdx.x;
    int w = tid >> 5, lane = tid & 31;
    int gg = lane >> 2, t4 = lane & 3;
    int m_base = (w >> 2)*32, n_base = (w & 3)*32;
    float acc[2][4][4] = {};
    int wr = tid >> 2, wc = (tid & 3)*8;
    int xr = tid >> 3, xc = (tid & 7)*16;
    for (int k0 = 0; k0 < CIN; k0 += 32){
        __syncthreads();
        #pragma unroll
        for (int j = 0; j < 2; j++){
            float4 v = *(const float4*)&Wt[(m0b+wr)*CIN + k0 + wc + j*4];
            Ws[wc+j*4+0][wr] = v.x; Ws[wc+j*4+1][wr] = v.y;
            Ws[wc+j*4+2][wr] = v.z; Ws[wc+j*4+3][wr] = v.w;
        }
        #pragma unroll
        for (int j = 0; j < 4; j++)
            *(float4*)&Xs[xr][xc+j*4] =
                *(const float4*)&Xb[(size_t)(k0+xr)*NPIX + n0b + xc + j*4];
        __syncthreads();
        #pragma unroll
        for (int kc = 0; kc < 4; kc++){
            int k8 = kc*8;
            unsigned ah[2][4], al[2][4], bh[4][2], bl[4][2];
            #pragma unroll
            for (int mt = 0; mt < 2; mt++){
                int m = m_base + mt*16 + gg;
                tfsplit(Ws[k8+t4  ][m  ], ah[mt][0], al[mt][0]);
                tfsplit(Ws[k8+t4  ][m+8], ah[mt][1], al[mt][1]);
                tfsplit(Ws[k8+t4+4][m  ], ah[mt][2], al[mt][2]);
                tfsplit(Ws[k8+t4+4][m+8], ah[mt][3], al[mt][3]);
            }
            #pragma unroll
            for (int nt = 0; nt < 4; nt++){
                int n = n_base + nt*8 + gg;
                tfsplit(Xs[k8+t4  ][n], bh[nt][0], bl[nt][0]);
                tfsplit(Xs[k8+t4+4][n], bh[nt][1], bl[nt][1]);
            }
            #pragma unroll
            for (int mt = 0; mt < 2; mt++)
                #pragma unroll
                for (int nt = 0; nt < 4; nt++)
                    mma3(acc[mt][nt], ah[mt], al[mt],
                         bh[nt][0], bh[nt][1], bl[nt][0], bl[nt][1]);
        }
    }
    #pragma unroll
    for (int mt = 0; mt < 2; mt++){
        int mrow0 = m0b + m_base + mt*16 + gg;
        float b0v = bias[mrow0], b1v = bias[mrow0+8];
        #pragma unroll
        for (int nt = 0; nt < 4; nt++){
            int col = n0b + n_base + nt*8 + 2*t4;
            *(float2*)&Yb[(size_t)mrow0*NPIX + col] =
                make_float2(acc[mt][nt][0]+b0v, acc[mt][nt][1]+b0v);
            *(float2*)&Yb[(size_t)(mrow0+8)*NPIX + col] =
                make_float2(acc[mt][nt][2]+b1v, acc[mt][nt][3]+b1v);
        }
    }
}

// -------- attention, 3xTF32 --------
#define SS_P 1032
#define QH_OFF (32*SS_P)               // 33024
#define QA_P 40
#define QL_OFF (QH_OFF + 128*QA_P)     // +5120
#define KS_OFF (QL_OFF + 128*QA_P)     // +5120
#define KB_P 72                        // phase B: Ks[ci 128][key 64] pitch 72
#define KD_P 136                       // phase D: Gs[key 64][ci 128] pitch 136
#define ATT_U32 (KS_OFF + 128*KB_P)    // 43264 + 9216 = 52480
#define ATT_BYTES (ATT_U32*4)          // 209920

__global__ __launch_bounds__(256) void attn_mma(
        const float* __restrict__ theta, const float* __restrict__ phi,
        const float* __restrict__ g, float* __restrict__ t){
    extern __shared__ unsigned sm[];
    unsigned* Ss = sm;              // [32][1032] scores/probs (fp32 bits)
    unsigned* Qh = sm + QH_OFF;     // [128][40] tf32 hi
    unsigned* Ql = sm + QL_OFF;     // [128][40] tf32 lo
    float*    Kf = (float*)(sm + KS_OFF);  // raw fp32: [128][72] or [64][136]
    int b = blockIdx.y, q0 = blockIdx.x*32;
    int tid = threadIdx.x, w = tid >> 5, lane = tid & 31;
    int gg = lane >> 2, t4 = lane & 3;
    const float* thb = theta + (size_t)b*CIc*NN4;
    const float* phb = phi   + (size_t)b*CIc*MM;
    const float* gbp = g     + (size_t)b*CIc*MM;

    // load Q^T (scaled), presplit hi/lo: Qh/Ql[ci][q]
    {
        int ci = tid >> 1, off = (tid & 1)*16;
        #pragma unroll
        for (int j = 0; j < 4; j++){
            float4 v = *(const float4*)&thb[(size_t)ci*NN4 + q0 + off + j*4];
            unsigned h, l; int base = ci*QA_P + off + j*4;
            tfsplit(v.x*SCALE, h, l); Qh[base+0]=h; Ql[base+0]=l;
            tfsplit(v.y*SCALE, h, l); Qh[base+1]=h; Ql[base+1]=l;
            tfsplit(v.z*SCALE, h, l); Qh[base+2]=h; Ql[base+2]=l;
            tfsplit(v.w*SCALE, h, l); Qh[base+3]=h; Ql[base+3]=l;
        }
    }

    // ---- phase B: S = Q^T @ K, key chunks of 64 ----
    int mB = (w >> 2)*16;     // query m-tile base (2 groups)
    int nB = (w & 3)*16;      // key subrange: 16 keys per warp, 2 n-tiles
    for (int ch = 0; ch < 16; ch++){
        int k0 = ch*64;
        __syncthreads();
        {   // load phi chunk raw fp32: Kf[ci][key]
            int ci = tid >> 1, off = (tid & 1)*32;
            #pragma unroll
            for (int j = 0; j < 8; j++)
                *(float4*)&Kf[ci*KB_P + off + j*4] =
                    *(const float4*)&phb[(size_t)ci*MM + k0 + off + j*4];
        }
        __syncthreads();
        float accB[2][4] = {};
        #pragma unroll 2
        for (int kc = 0; kc < 16; kc++){
            int k8 = kc*8;
            unsigned ah[4], al[4];
            ah[0]=Qh[(k8+t4  )*QA_P + mB+gg];   al[0]=Ql[(k8+t4  )*QA_P + mB+gg];
            ah[1]=Qh[(k8+t4  )*QA_P + mB+gg+8]; al[1]=Ql[(k8+t4  )*QA_P + mB+gg+8];
            ah[2]=Qh[(k8+t4+4)*QA_P + mB+gg];   al[2]=Ql[(k8+t4+4)*QA_P + mB+gg];
            ah[3]=Qh[(k8+t4+4)*QA_P + mB+gg+8]; al[3]=Ql[(k8+t4+4)*QA_P + mB+gg+8];
            #pragma unroll
            for (int nt = 0; nt < 2; nt++){
                unsigned bh0,bl0,bh1,bl1;
                tfsplit(Kf[(k8+t4  )*KB_P + nB + nt*8 + gg], bh0, bl0);
                tfsplit(Kf[(k8+t4+4)*KB_P + nB + nt*8 + gg], bh1, bl1);
                mma3(accB[nt], ah, al, bh0, bh1, bl0, bl1);
            }
        }
        #pragma unroll
        for (int nt = 0; nt < 2; nt++){
            int col = k0 + nB + nt*8 + 2*t4;
            *(float2*)((float*)Ss + (mB+gg  )*SS_P + col) = make_float2(accB[nt][0], accB[nt][1]);
            *(float2*)((float*)Ss + (mB+gg+8)*SS_P + col) = make_float2(accB[nt][2], accB[nt][3]);
        }
    }
    __syncthreads();

    // ---- phase C: softmax rows ----
    for (int r = w; r < 32; r += 8){
        float* rowp = (float*)Ss + r*SS_P;
        float mx = -1e30f;
        for (int i = lane; i < 1024; i += 32) mx = fmaxf(mx, rowp[i]);
        #pragma unroll
        for (int o = 16; o; o >>= 1) mx = fmaxf(mx, __shfl_xor_sync(0xffffffffu, mx, o));
        float sum = 0.f;
        for (int i = lane; i < 1024; i += 32){
            float e = __expf(rowp[i] - mx); rowp[i] = e; sum += e;
        }
        #pragma unroll
        for (int o = 16; o; o >>= 1) sum += __shfl_xor_sync(0xffffffffu, sum, o);
        float inv = 1.f/sum;
        for (int i = lane; i < 1024; i += 32) rowp[i] *= inv;
    }

    // ---- phase D: t = G @ P^T, key chunks of 64 ----
    int mD = (w >> 1)*32;   // ci m-base: 2 m-tiles
    int nD = (w & 1)*16;    // q n-base: 2 n-tiles
    float accD[2][2][4] = {};
    for (int ch = 0; ch < 16; ch++){
        int k0 = ch*64;
        __syncthreads();
        {   // load g chunk transposed raw fp32: Kf[key][ci]
            int ci = tid >> 1, off = (tid & 1)*32;
            #pragma unroll
            for (int j = 0; j < 8; j++){
                float4 v = *(const float4*)&gbp[(size_t)ci*MM + k0 + off + j*4];
                Kf[(off+j*4+0)*KD_P + ci] = v.x;
                Kf[(off+j*4+1)*KD_P + ci] = v.y;
                Kf[(off+j*4+2)*KD_P + ci] = v.z;
                Kf[(off+j*4+3)*KD_P + ci] = v.w;
            }
        }
        __syncthreads();
        #pragma unroll 2
        for (int kc = 0; kc < 8; kc++){
            int k8 = kc*8;
            unsigned ah[2][4], al[2][4];
            #pragma unroll
            for (int mt = 0; mt < 2; mt++){
                int m = mD + mt*16 + gg;
                tfsplit(Kf[(k8+t4  )*KD_P + m  ], ah[mt][0], al[mt][0]);
                tfsplit(Kf[(k8+t4  )*KD_P + m+8], ah[mt][1], al[mt][1]);
                tfsplit(Kf[(k8+t4+4)*KD_P + m  ], ah[mt][2], al[mt][2]);
                tfsplit(Kf[(k8+t4+4)*KD_P + m+8], ah[mt][3], al[mt][3]);
            }
            #pragma unroll
            for (int nt = 0; nt < 2; nt++){
                unsigned bh0,bl0,bh1,bl1;
                tfsplit(((float*)Ss)[(nD+nt*8+gg)*SS_P + k0 + k8 + t4    ], bh0, bl0);
                tfsplit(((float*)Ss)[(nD+nt*8+gg)*SS_P + k0 + k8 + t4 + 4], bh1, bl1);
                #pragma unroll
                for (int mt = 0; mt < 2; mt++)
                    mma3(accD[mt][nt], ah[mt], al[mt], bh0, bh1, bl0, bl1);
            }
        }
    }
    float* tb = t + (size_t)b*CIc*NN4;
    #pragma unroll
    for (int mt = 0; mt < 2; mt++){
        int ci0 = mD + mt*16 + gg;
        #pragma unroll
        for (int nt = 0; nt < 2; nt++){
            int col = q0 + nD + nt*8 + 2*t4;
            *(float2*)&tb[(size_t)ci0*NN4 + col] =
                make_float2(accD[mt][nt][0], accD[mt][nt][1]);
            *(float2*)&tb[(size_t)(ci0+8)*NN4 + col] =
                make_float2(accD[mt][nt][2], accD[mt][nt][3]);
        }
    }
}

// -------- per-channel batch statistics (fp64 accumulate, deterministic) --------
__global__ void stats_kernel(const float* __restrict__ z, float* __restrict__ stats){
    __shared__ double sd[256], sd2[256];
    int c = blockIdx.x, tid = threadIdx.x;
    double s = 0.0, s2 = 0.0;
    for (int i = tid; i < BB*NN4; i += 256){
        int b = i >> 12, n = i & 4095;
        float v = z[((size_t)b*CC + c)*NN4 + n];
        s += v; s2 += (double)v*v;
    }
    sd[tid] = s; sd2[tid] = s2;
    __syncthreads();
    for (int o = 128; o; o >>= 1){
        if (tid < o){ sd[tid] += sd[tid+o]; sd2[tid] += sd2[tid+o]; }
        __syncthreads();
    }
    if (tid == 0){
        double cnt = (double)(BB*NN4);
        double mean = sd[0]/cnt;
        double var  = sd2[0]/cnt - mean*mean;
        stats[c]      = (float)mean;
        stats[CC + c] = rsqrtf((float)var + EPSF);
    }
}

// -------- normalize + affine + residual --------
__global__ void finalize_kernel(const float* __restrict__ x, const float* __restrict__ z,
                                const float* __restrict__ stats,
                                const float* __restrict__ gamma, const float* __restrict__ beta,
                                float* __restrict__ out){
    int i4 = blockIdx.x*256 + threadIdx.x;
    int c = (i4 >> 10) & 255;
    float a  = stats[CC + c] * gamma[c];
    float bc = beta[c] - stats[c]*a;
    float4 xv = ((const float4*)x)[i4];
    float4 zv = ((const float4*)z)[i4];
    float4 o;
    o.x = xv.x + zv.x*a + bc;
    o.y = xv.y + zv.y*a + bc;
    o.z = xv.z + zv.z*a + bc;
    o.w = xv.w + zv.w*a + bc;
    ((float4*)out)[i4] = o;
}

extern "C" void kernel_launch(void* const* d_in, const int* in_sizes, int n_in,
                              void* d_out, int out_size){
    const float* x       = (const float*)d_in[0];
    const float* theta_w = (const float*)d_in[1];
    const float* theta_b = (const float*)d_in[2];
    const float* phi_w   = (const float*)d_in[3];
    const float* phi_b   = (const float*)d_in[4];
    const float* g_w     = (const float*)d_in[5];
    const float* g_b     = (const float*)d_in[6];
    const float* wz_w    = (const float*)d_in[7];
    const float* wz_b    = (const float*)d_in[8];
    const float* gamma   = (const float*)d_in[9];
    const float* beta    = (const float*)d_in[10];
    float* out = (float*)d_out;

    float *xp, *theta, *phi, *g, *t, *z, *stats;
    cudaGetSymbolAddress((void**)&xp,    d_xp);
    cudaGetSymbolAddress((void**)&theta, d_theta);
    cudaGetSymbolAddress((void**)&phi,   d_phi);
    cudaGetSymbolAddress((void**)&g,     d_g);
    cudaGetSymbolAddress((void**)&t,     d_t);
    cudaGetSymbolAddress((void**)&z,     d_z);
    cudaGetSymbolAddress((void**)&stats, d_stats);

    cudaFuncSetAttribute(attn_mma, cudaFuncAttributeMaxDynamicSharedMemorySize,
                         ATT_BYTES);

    pool_kernel<<<(BB*CC*MM)/256, 256>>>(x, xp);
    conv_mma<CIc, CC, NN4><<<dim3(NN4/128, CIc/64, BB), 256>>>(x,  theta_w, theta_b, theta);
    conv_mma<CIc, CC, MM ><<<dim3(MM/128,  CIc/64, BB), 256>>>(xp, phi_w,   phi_b,   phi);
    conv_mma<CIc, CC, MM ><<<dim3(MM/128,  CIc/64, BB), 256>>>(xp, g_w,     g_b,     g);
    attn_mma<<<dim3(NN4/32, BB), 256, ATT_BYTES>>>(theta, phi, g, t);
    conv_mma<CC, CIc, NN4><<<dim3(NN4/128, CC/64, BB), 256>>>(t, wz_w, wz_b, z);
    stats_kernel<<<CC, 256>>>(z, stats);
    finalize_kernel<<<(BB*CC*NN4/4)/256, 256>>>(x, z, stats, gamma, beta, out);
}

// round 4
// speedup vs baseline: 2.2909x; 1.9396x over previous
#include <cuda_runtime.h>
#include <math.h>

#define BB 8
#define CC 256
#define CIc 128
#define HH 64
#define WW 64
#define NN4 4096
#define MM 1024
#define EPSF 1e-5f
#define SCALE 0.08838834764831845f  // 1/sqrt(128)

// -------- scratch (static device globals; no allocation) --------
__device__ float d_xp[BB*CC*MM];
__device__ float d_theta[BB*CIc*NN4];
__device__ float d_phi[BB*CIc*MM];
__device__ float d_g[BB*CIc*MM];
__device__ float d_s[(size_t)BB*NN4*MM];   // scores / probs (134MB)
__device__ float d_t[BB*CIc*NN4];
__device__ float d_z[BB*CC*NN4];
__device__ float d_stats[2*CC];

// -------- helpers --------
__device__ __forceinline__ unsigned f2tf(float f){
    unsigned r; asm("cvt.rna.tf32.f32 %0, %1;" : "=r"(r) : "f"(f)); return r;
}
__device__ __forceinline__ void tfsplit(float v, unsigned &hi, unsigned &lo){
    hi = f2tf(v);
    lo = f2tf(v - __uint_as_float(hi));
}
__device__ __forceinline__ void mma_tf32(float c[4], unsigned a0, unsigned a1,
                                         unsigned a2, unsigned a3,
                                         unsigned b0, unsigned b1){
    asm("mma.sync.aligned.m16n8k8.row.col.f32.tf32.tf32.f32 "
        "{%0,%1,%2,%3},{%4,%5,%6,%7},{%8,%9},{%0,%1,%2,%3};"
        : "+f"(c[0]), "+f"(c[1]), "+f"(c[2]), "+f"(c[3])
        : "r"(a0), "r"(a1), "r"(a2), "r"(a3), "r"(b0), "r"(b1));
}
__device__ __forceinline__ void mma3(float c[4],
        const unsigned ah[4], const unsigned al[4],
        unsigned bh0, unsigned bh1, unsigned bl0, unsigned bl1){
    mma_tf32(c, ah[0],ah[1],ah[2],ah[3], bh0,bh1);
    mma_tf32(c, ah[0],ah[1],ah[2],ah[3], bl0,bl1);
    mma_tf32(c, al[0],al[1],al[2],al[3], bh0,bh1);
}

// -------- 2x2 maxpool stride 2 --------
__global__ void pool_kernel(const float* __restrict__ x, float* __restrict__ xp){
    int e = blockIdx.x*256 + threadIdx.x;
    int p = e & 1023; int bc = e >> 10;
    int i = p >> 5, j = p & 31;
    const float* base = x + ((bc*HH + 2*i)*WW + 2*j);
    xp[e] = fmaxf(fmaxf(base[0], base[1]), fmaxf(base[WW], base[WW+1]));
}

// -------- 1x1 conv, 3xTF32, split-at-store --------
// block 64(M) x 128(N), 8 warps 2x4, warp 32x32. smem hi/lo planes.
#define CWP 72
#define CXP 136
#define CONV_SMEM_U32 (32*CWP*2 + 32*CXP*2)
template<int CO, int CIN, int NPIX>
__global__ __launch_bounds__(256) void conv_mma(
        const float* __restrict__ X, const float* __restrict__ Wt,
        const float* __restrict__ bias, float* __restrict__ Y){
    extern __shared__ unsigned dy[];
    unsigned (*Wh)[CWP] = (unsigned(*)[CWP])dy;
    unsigned (*Wl)[CWP] = (unsigned(*)[CWP])(dy + 32*CWP);
    unsigned (*Xh)[CXP] = (unsigned(*)[CXP])(dy + 64*CWP);
    unsigned (*Xl)[CXP] = (unsigned(*)[CXP])(dy + 64*CWP + 32*CXP);
    int b = blockIdx.z;
    const float* Xb = X + (size_t)b*CIN*NPIX;
    float* Yb = Y + (size_t)b*CO*NPIX;
    int m0b = blockIdx.y*64, n0b = blockIdx.x*128;
    int tid = threadIdx.x;
    int w = tid >> 5, lane = tid & 31;
    int gg = lane >> 2, t4 = lane & 3;
    int m_base = (w >> 2)*32, n_base = (w & 3)*32;
    float acc[2][4][4] = {};
    int wm = tid & 63, wkg = (tid >> 6)*8;       // W: 64 m x 32 k per chunk
    int xr = tid >> 3, xc0 = (tid & 7)*4;        // X: 32 k x 128 n
    for (int k0 = 0; k0 < CIN; k0 += 32){
        __syncthreads();
        {
            const float* wp = &Wt[(m0b+wm)*CIN + k0 + wkg];
            float4 v0 = *(const float4*)wp;
            float4 v1 = *(const float4*)(wp+4);
            unsigned h,l;
            tfsplit(v0.x,h,l); Wh[wkg+0][wm]=h; Wl[wkg+0][wm]=l;
            tfsplit(v0.y,h,l); Wh[wkg+1][wm]=h; Wl[wkg+1][wm]=l;
            tfsplit(v0.z,h,l); Wh[wkg+2][wm]=h; Wl[wkg+2][wm]=l;
            tfsplit(v0.w,h,l); Wh[wkg+3][wm]=h; Wl[wkg+3][wm]=l;
            tfsplit(v1.x,h,l); Wh[wkg+4][wm]=h; Wl[wkg+4][wm]=l;
            tfsplit(v1.y,h,l); Wh[wkg+5][wm]=h; Wl[wkg+5][wm]=l;
            tfsplit(v1.z,h,l); Wh[wkg+6][wm]=h; Wl[wkg+6][wm]=l;
            tfsplit(v1.w,h,l); Wh[wkg+7][wm]=h; Wl[wkg+7][wm]=l;
        }
        #pragma unroll
        for (int j = 0; j < 4; j++){
            float4 v = *(const float4*)&Xb[(size_t)(k0+xr)*NPIX + n0b + xc0 + 32*j];
            uint4 h, l;
            tfsplit(v.x, h.x, l.x); tfsplit(v.y, h.y, l.y);
            tfsplit(v.z, h.z, l.z); tfsplit(v.w, h.w, l.w);
            *(uint4*)&Xh[xr][xc0+32*j] = h;
            *(uint4*)&Xl[xr][xc0+32*j] = l;
        }
        __syncthreads();
        #pragma unroll
        for (int kc = 0; kc < 4; kc++){
            int k8 = kc*8;
            unsigned ah[2][4], al[2][4];
            #pragma unroll
            for (int mt = 0; mt < 2; mt++){
                int m = m_base + mt*16 + gg;
                ah[mt][0]=Wh[k8+t4  ][m];   al[mt][0]=Wl[k8+t4  ][m];
                ah[mt][1]=Wh[k8+t4  ][m+8]; al[mt][1]=Wl[k8+t4  ][m+8];
                ah[mt][2]=Wh[k8+t4+4][m];   al[mt][2]=Wl[k8+t4+4][m];
                ah[mt][3]=Wh[k8+t4+4][m+8]; al[mt][3]=Wl[k8+t4+4][m+8];
            }
            #pragma unroll
            for (int nt = 0; nt < 4; nt++){
                int n = n_base + nt*8 + gg;
                unsigned bh0=Xh[k8+t4][n], bh1=Xh[k8+t4+4][n];
                unsigned bl0=Xl[k8+t4][n], bl1=Xl[k8+t4+4][n];
                mma3(acc[0][nt], ah[0], al[0], bh0,bh1,bl0,bl1);
                mma3(acc[1][nt], ah[1], al[1], bh0,bh1,bl0,bl1);
            }
        }
    }
    #pragma unroll
    for (int mt = 0; mt < 2; mt++){
        int mrow0 = m0b + m_base + mt*16 + gg;
        float b0v = bias[mrow0], b1v = bias[mrow0+8];
        #pragma unroll
        for (int nt = 0; nt < 4; nt++){
            int col = n0b + n_base + nt*8 + 2*t4;
            *(float2*)&Yb[(size_t)mrow0*NPIX + col] =
                make_float2(acc[mt][nt][0]+b0v, acc[mt][nt][1]+b0v);
            *(float2*)&Yb[(size_t)(mrow0+8)*NPIX + col] =
                make_float2(acc[mt][nt][2]+b1v, acc[mt][nt][3]+b1v);
        }
    }
}

// -------- scores: S[b](4096,1024) = (theta^T * SCALE) @ phi --------
// block 128x128, 8 warps 4x2, warp 32x64. K=128 (ci).
#define GP 136
#define SC_SMEM_U32 (4*32*GP)
__global__ __launch_bounds__(256) void score_mma(
        const float* __restrict__ theta, const float* __restrict__ phi,
        float* __restrict__ S){
    extern __shared__ unsigned dy[];
    unsigned (*Ah)[GP] = (unsigned(*)[GP])dy;
    unsigned (*Al)[GP] = (unsigned(*)[GP])(dy + 32*GP);
    unsigned (*Bh)[GP] = (unsigned(*)[GP])(dy + 64*GP);
    unsigned (*Bl)[GP] = (unsigned(*)[GP])(dy + 96*GP);
    int b = blockIdx.z;
    const float* thb = theta + (size_t)b*CIc*NN4;
    const float* phb = phi   + (size_t)b*CIc*MM;
    float* Sb = S + (size_t)b*NN4*MM;
    int m0 = blockIdx.y*128, n0 = blockIdx.x*128;
    int tid = threadIdx.x, w = tid >> 5, lane = tid & 31;
    int gg = lane >> 2, t4 = lane & 3;
    int wm = (w >> 1)*32, wn = (w & 1)*64;
    float acc[2][8][4] = {};
    int r = tid >> 3, c0 = (tid & 7)*4;
    #pragma unroll 1
    for (int k0 = 0; k0 < CIc; k0 += 32){
        __syncthreads();
        #pragma unroll
        for (int j = 0; j < 4; j++){
            float4 va = *(const float4*)&thb[(size_t)(k0+r)*NN4 + m0 + c0 + 32*j];
            uint4 h, l;
            tfsplit(va.x*SCALE, h.x, l.x); tfsplit(va.y*SCALE, h.y, l.y);
            tfsplit(va.z*SCALE, h.z, l.z); tfsplit(va.w*SCALE, h.w, l.w);
            *(uint4*)&Ah[r][c0+32*j] = h;
            *(uint4*)&Al[r][c0+32*j] = l;
            float4 vb = *(const float4*)&phb[(size_t)(k0+r)*MM + n0 + c0 + 32*j];
            tfsplit(vb.x, h.x, l.x); tfsplit(vb.y, h.y, l.y);
            tfsplit(vb.z, h.z, l.z); tfsplit(vb.w, h.w, l.w);
            *(uint4*)&Bh[r][c0+32*j] = h;
            *(uint4*)&Bl[r][c0+32*j] = l;
        }
        __syncthreads();
        #pragma unroll
        for (int kc = 0; kc < 4; kc++){
            int k8 = kc*8;
            unsigned ah[2][4], al[2][4];
            #pragma unroll
            for (int mt = 0; mt < 2; mt++){
                int m = wm + mt*16 + gg;
                ah[mt][0]=Ah[k8+t4  ][m];   al[mt][0]=Al[k8+t4  ][m];
                ah[mt][1]=Ah[k8+t4  ][m+8]; al[mt][1]=Al[k8+t4  ][m+8];
                ah[mt][2]=Ah[k8+t4+4][m];   al[mt][2]=Al[k8+t4+4][m];
                ah[mt][3]=Ah[k8+t4+4][m+8]; al[mt][3]=Al[k8+t4+4][m+8];
            }
            #pragma unroll
            for (int nt = 0; nt < 8; nt++){
                int n = wn + nt*8 + gg;
                unsigned bh0=Bh[k8+t4][n], bh1=Bh[k8+t4+4][n];
                unsigned bl0=Bl[k8+t4][n], bl1=Bl[k8+t4+4][n];
                mma3(acc[0][nt], ah[0], al[0], bh0,bh1,bl0,bl1);
                mma3(acc[1][nt], ah[1], al[1], bh0,bh1,bl0,bl1);
            }
        }
    }
    #pragma unroll
    for (int mt = 0; mt < 2; mt++){
        int row0 = m0 + wm + mt*16 + gg;
        #pragma unroll
        for (int nt = 0; nt < 8; nt++){
            int col = n0 + wn + nt*8 + 2*t4;
            *(float2*)&Sb[(size_t)row0*MM + col] =
                make_float2(acc[mt][nt][0], acc[mt][nt][1]);
            *(float2*)&Sb[(size_t)(row0+8)*MM + col] =
                make_float2(acc[mt][nt][2], acc[mt][nt][3]);
        }
    }
}

// -------- softmax rows in place: 8 rows per 256-thr block --------
__global__ void softmax_kernel(float* __restrict__ S){
    int row = blockIdx.x*8 + (threadIdx.x >> 5);
    int lane = threadIdx.x & 31;
    float4* rp = (float4*)(S + (size_t)row*MM);
    float4 v[8];
    float mx = -1e30f;
    #pragma unroll
    for (int j = 0; j < 8; j++){
        v[j] = rp[lane + 32*j];
        mx = fmaxf(mx, fmaxf(fmaxf(v[j].x, v[j].y), fmaxf(v[j].z, v[j].w)));
    }
    #pragma unroll
    for (int o = 16; o; o >>= 1) mx = fmaxf(mx, __shfl_xor_sync(0xffffffffu, mx, o));
    float sum = 0.f;
    #pragma unroll
    for (int j = 0; j < 8; j++){
        v[j].x = __expf(v[j].x - mx); v[j].y = __expf(v[j].y - mx);
        v[j].z = __expf(v[j].z - mx); v[j].w = __expf(v[j].w - mx);
        sum += v[j].x + v[j].y + v[j].z + v[j].w;
    }
    #pragma unroll
    for (int o = 16; o; o >>= 1) sum += __shfl_xor_sync(0xffffffffu, sum, o);
    float inv = 1.f/sum;
    #pragma unroll
    for (int j = 0; j < 8; j++){
        v[j].x *= inv; v[j].y *= inv; v[j].z *= inv; v[j].w *= inv;
        rp[lane + 32*j] = v[j];
    }
}

// -------- t[b](128,4096) = g(128,1024) @ P^T(1024,4096) --------
// block 128(M=ci) x 128(N=q), 8 warps 4x2, warp 32x64. K=1024 chunks of 32.
// A tile: g transposed [k32][ci128] pitch GP; B tile: P n-major [n128][k32] pitch 36.
#define PBP 36
#define PV_SMEM_U32 (2*32*GP + 2*128*PBP)
__global__ __launch_bounds__(256) void pv_mma(
        const float* __restrict__ g, const float* __restrict__ P,
        float* __restrict__ T){
    extern __shared__ unsigned dy[];
    unsigned (*Ah)[GP]  = (unsigned(*)[GP])dy;
    unsigned (*Al)[GP]  = (unsigned(*)[GP])(dy + 32*GP);
    unsigned (*Bh)[PBP] = (unsigned(*)[PBP])(dy + 64*GP);
    unsigned (*Bl)[PBP] = (unsigned(*)[PBP])(dy + 64*GP + 128*PBP);
    int b = blockIdx.z;
    const float* gb = g + (size_t)b*CIc*MM;
    const float* Pb = P + (size_t)b*NN4*MM;
    float* Tb = T + (size_t)b*CIc*NN4;
    int n0 = blockIdx.x*128;
    int tid = threadIdx.x, w = tid >> 5, lane = tid & 31;
    int gg = lane >> 2, t4 = lane & 3;
    int wm = (w >> 1)*32, wn = (w & 1)*64;
    float acc[2][8][4] = {};
    int aci = tid >> 1, ak0 = (tid & 1)*16;      // A load: 2 thr per ci row
    int bn = tid >> 3, bk0 = (tid & 7)*4;        // B load: 8 thr per P row
    #pragma unroll 1
    for (int k0 = 0; k0 < MM; k0 += 32){
        __syncthreads();
        #pragma unroll
        for (int j = 0; j < 4; j++){
            float4 v = *(const float4*)&gb[(size_t)aci*MM + k0 + ak0 + 4*j];
            unsigned h,l; int kk = ak0 + 4*j;
            tfsplit(v.x,h,l); Ah[kk+0][aci]=h; Al[kk+0][aci]=l;
            tfsplit(v.y,h,l); Ah[kk+1][aci]=h; Al[kk+1][aci]=l;
            tfsplit(v.z,h,l); Ah[kk+2][aci]=h; Al[kk+2][aci]=l;
            tfsplit(v.w,h,l); Ah[kk+3][aci]=h; Al[kk+3][aci]=l;
        }
        #pragma unroll
        for (int p = 0; p < 4; p++){
            int n = bn + 32*p;
            float4 v = *(const float4*)&Pb[(size_t)(n0+n)*MM + k0 + bk0];
            uint4 h, l;
            tfsplit(v.x, h.x, l.x); tfsplit(v.y, h.y, l.y);
            tfsplit(v.z, h.z, l.z); tfsplit(v.w, h.w, l.w);
            *(uint4*)&Bh[n][bk0] = h;
            *(uint4*)&Bl[n][bk0] = l;
        }
        __syncthreads();
        #pragma unroll
        for (int kc = 0; kc < 4; kc++){
            int k8 = kc*8;
            unsigned ah[2][4], al[2][4];
            #pragma unroll
            for (int mt = 0; mt < 2; mt++){
                int m = wm + mt*16 + gg;
                ah[mt][0]=Ah[k8+t4  ][m];   al[mt][0]=Al[k8+t4  ][m];
                ah[mt][1]=Ah[k8+t4  ][m+8]; al[mt][1]=Al[k8+t4  ][m+8];
                ah[mt][2]=Ah[k8+t4+4][m];   al[mt][2]=Al[k8+t4+4][m];
                ah[mt][3]=Ah[k8+t4+4][m+8]; al[mt][3]=Al[k8+t4+4][m+8];
            }
            #pragma unroll
            for (int nt = 0; nt < 8; nt++){
                int n = wn + nt*8 + gg;
                unsigned bh0=Bh[n][k8+t4], bh1=Bh[n][k8+t4+4];
                unsigned bl0=Bl[n][k8+t4], bl1=Bl[n][k8+t4+4];
                mma3(acc[0][nt], ah[0], al[0], bh0,bh1,bl0,bl1);
                mma3(acc[1][nt], ah[1], al[1], bh0,bh1,bl0,bl1);
            }
        }
    }
    #pragma unroll
    for (int mt = 0; mt < 2; mt++){
        int row0 = wm + mt*16 + gg;
        #pragma unroll
        for (int nt = 0; nt < 8; nt++){
            int col = n0 + wn + nt*8 + 2*t4;
            *(float2*)&Tb[(size_t)row0*NN4 + col] =
                make_float2(acc[mt][nt][0], acc[mt][nt][1]);
            *(float2*)&Tb[(size_t)(row0+8)*NN4 + col] =
                make_float2(acc[mt][nt][2], acc[mt][nt][3]);
        }
    }
}

// -------- per-channel batch statistics (fp64 accumulate, deterministic) --------
__global__ void stats_kernel(const float* __restrict__ z, float* __restrict__ stats){
    __shared__ double sd[256], sd2[256];
    int c = blockIdx.x, tid = threadIdx.x;
    double s = 0.0, s2 = 0.0;
    for (int i = tid; i < BB*NN4; i += 256){
        int b = i >> 12, n = i & 4095;
        float v = z[((size_t)b*CC + c)*NN4 + n];
        s += v; s2 += (double)v*v;
    }
    sd[tid] = s; sd2[tid] = s2;
    __syncthreads();
    for (int o = 128; o; o >>= 1){
        if (tid < o){ sd[tid] += sd[tid+o]; sd2[tid] += sd2[tid+o]; }
        __syncthreads();
    }
    if (tid == 0){
        double cnt = (double)(BB*NN4);
        double mean = sd[0]/cnt;
        double var  = sd2[0]/cnt - mean*mean;
        stats[c]      = (float)mean;
        stats[CC + c] = rsqrtf((float)var + EPSF);
    }
}

// -------- normalize + affine + residual --------
__global__ void finalize_kernel(const float* __restrict__ x, const float* __restrict__ z,
                                const float* __restrict__ stats,
                                const float* __restrict__ gamma, const float* __restrict__ beta,
                                float* __restrict__ out){
    int i4 = blockIdx.x*256 + threadIdx.x;
    int c = (i4 >> 10) & 255;
    float a  = stats[CC + c] * gamma[c];
    float bc = beta[c] - stats[c]*a;
    float4 xv = ((const float4*)x)[i4];
    float4 zv = ((const float4*)z)[i4];
    float4 o;
    o.x = xv.x + zv.x*a + bc;
    o.y = xv.y + zv.y*a + bc;
    o.z = xv.z + zv.z*a + bc;
    o.w = xv.w + zv.w*a + bc;
    ((float4*)out)[i4] = o;
}

extern "C" void kernel_launch(void* const* d_in, const int* in_sizes, int n_in,
                              void* d_out, int out_size){
    const float* x       = (const float*)d_in[0];
    const float* theta_w = (const float*)d_in[1];
    const float* theta_b = (const float*)d_in[2];
    const float* phi_w   = (const float*)d_in[3];
    const float* phi_b   = (const float*)d_in[4];
    const float* g_w     = (const float*)d_in[5];
    const float* g_b     = (const float*)d_in[6];
    const float* wz_w    = (const float*)d_in[7];
    const float* wz_b    = (const float*)d_in[8];
    const float* gamma   = (const float*)d_in[9];
    const float* beta    = (const float*)d_in[10];
    float* out = (float*)d_out;

    float *xp, *theta, *phi, *g, *s, *t, *z, *stats;
    cudaGetSymbolAddress((void**)&xp,    d_xp);
    cudaGetSymbolAddress((void**)&theta, d_theta);
    cudaGetSymbolAddress((void**)&phi,   d_phi);
    cudaGetSymbolAddress((void**)&g,     d_g);
    cudaGetSymbolAddress((void**)&s,     d_s);
    cudaGetSymbolAddress((void**)&t,     d_t);
    cudaGetSymbolAddress((void**)&z,     d_z);
    cudaGetSymbolAddress((void**)&stats, d_stats);

    cudaFuncSetAttribute(conv_mma<CIc, CC, NN4>,
        cudaFuncAttributeMaxDynamicSharedMemorySize, CONV_SMEM_U32*4);
    cudaFuncSetAttribute(conv_mma<CIc, CC, MM>,
        cudaFuncAttributeMaxDynamicSharedMemorySize, CONV_SMEM_U32*4);
    cudaFuncSetAttribute(conv_mma<CC, CIc, NN4>,
        cudaFuncAttributeMaxDynamicSharedMemorySize, CONV_SMEM_U32*4);
    cudaFuncSetAttribute(score_mma,
        cudaFuncAttributeMaxDynamicSharedMemorySize, SC_SMEM_U32*4);
    cudaFuncSetAttribute(pv_mma,
        cudaFuncAttributeMaxDynamicSharedMemorySize, PV_SMEM_U32*4);

    pool_kernel<<<(BB*CC*MM)/256, 256>>>(x, xp);
    conv_mma<CIc, CC, NN4><<<dim3(NN4/128, CIc/64, BB), 256, CONV_SMEM_U32*4>>>(
        x,  theta_w, theta_b, theta);
    conv_mma<CIc, CC, MM ><<<dim3(MM/128,  CIc/64, BB), 256, CONV_SMEM_U32*4>>>(
        xp, phi_w,   phi_b,   phi);
    conv_mma<CIc, CC, MM ><<<dim3(MM/128,  CIc/64, BB), 256, CONV_SMEM_U32*4>>>(
        xp, g_w,     g_b,     g);
    score_mma<<<dim3(MM/128, NN4/128, BB), 256, SC_SMEM_U32*4>>>(theta, phi, s);
    softmax_kernel<<<(BB*NN4)/8, 256>>>(s);
    pv_mma<<<dim3(NN4/128, 1, BB), 256, PV_SMEM_U32*4>>>(g, s, t);
    conv_mma<CC, CIc, NN4><<<dim3(NN4/128, CC/64, BB), 256, CONV_SMEM_U32*4>>>(
        t, wz_w, wz_b, z);
    stats_kernel<<<CC, 256>>>(z, stats);
    finalize_kernel<<<(BB*CC*NN4/4)/256, 256>>>(x, z, stats, gamma, beta, out);
}